// round 6
// baseline (speedup 1.0000x reference)
#include <cuda_runtime.h>
#include <math.h>

#define BATCH 8
#define LSEQ  1024
#define BL    8192
#define DM    256
#define DIN   512
#define DPROJ 1160
#define CONVD 640
#define NH    8
#define HD    64
#define DS    64

// ---------------- scratch (device globals; no runtime allocation) ------------
__device__ float g_zx[BL * DPROJ];    // in_proj output (zxbcdt)     ~38 MB
__device__ float g_xbc[BL * CONVD];   // conv+silu output            ~21 MB
__device__ float g_dt[BL * NH];
__device__ float g_dA[BL * NH];
__device__ float g_ypre[BL * DIN];    // scan output incl. D*x       ~17 MB
__device__ float g_ynorm[BL * DIN];   // gated + rmsnormed
__device__ float g_h[BL * DM];        // hidden between the 2 blocks

// ---------------- SGEMM: C[M,N] = A[M,K] * W[N,K]^T  (both K-contiguous) -----
// BM=BN=128, BK=16, 256 threads, 8x8 microtile. M%128==0, K%16==0 assumed;
// N guarded (N=1160 case).
__global__ __launch_bounds__(256) void sgemm_nt(
    const float* __restrict__ A, const float* __restrict__ W,
    float* __restrict__ C, int M, int N, int K) {
  __shared__ float As[16][128];
  __shared__ float Ws[16][128];
  const int tid = threadIdx.x;
  const int tx = tid & 15;        // n-dir
  const int ty = tid >> 4;        // m-dir
  const int m0 = blockIdx.y * 128;
  const int n0 = blockIdx.x * 128;
  const int lr = tid >> 2;        // 0..63 row for loads
  const int lc = (tid & 3) * 4;   // 0,4,8,12 col for loads

  float acc[8][8];
#pragma unroll
  for (int i = 0; i < 8; i++)
#pragma unroll
    for (int j = 0; j < 8; j++) acc[i][j] = 0.f;

  for (int k0 = 0; k0 < K; k0 += 16) {
#pragma unroll
    for (int rr = 0; rr < 2; rr++) {
      int m = m0 + lr + rr * 64;
      float4 v = *reinterpret_cast<const float4*>(A + (size_t)m * K + k0 + lc);
      As[lc + 0][lr + rr * 64] = v.x;
      As[lc + 1][lr + rr * 64] = v.y;
      As[lc + 2][lr + rr * 64] = v.z;
      As[lc + 3][lr + rr * 64] = v.w;
    }
#pragma unroll
    for (int rr = 0; rr < 2; rr++) {
      int n = n0 + lr + rr * 64;
      float4 v = make_float4(0.f, 0.f, 0.f, 0.f);
      if (n < N)
        v = *reinterpret_cast<const float4*>(W + (size_t)n * K + k0 + lc);
      Ws[lc + 0][lr + rr * 64] = v.x;
      Ws[lc + 1][lr + rr * 64] = v.y;
      Ws[lc + 2][lr + rr * 64] = v.z;
      Ws[lc + 3][lr + rr * 64] = v.w;
    }
    __syncthreads();
#pragma unroll
    for (int kk = 0; kk < 16; kk++) {
      float a[8], b[8];
      *reinterpret_cast<float4*>(&a[0]) = *reinterpret_cast<const float4*>(&As[kk][ty * 8]);
      *reinterpret_cast<float4*>(&a[4]) = *reinterpret_cast<const float4*>(&As[kk][ty * 8 + 4]);
      *reinterpret_cast<float4*>(&b[0]) = *reinterpret_cast<const float4*>(&Ws[kk][tx * 8]);
      *reinterpret_cast<float4*>(&b[4]) = *reinterpret_cast<const float4*>(&Ws[kk][tx * 8 + 4]);
#pragma unroll
      for (int i = 0; i < 8; i++)
#pragma unroll
        for (int j = 0; j < 8; j++)
          acc[i][j] = fmaf(a[i], b[j], acc[i][j]);
    }
    __syncthreads();
  }

#pragma unroll
  for (int i = 0; i < 8; i++) {
    int m = m0 + ty * 8 + i;
    float* crow = C + (size_t)m * N;
#pragma unroll
    for (int j4 = 0; j4 < 8; j4 += 4) {
      int n = n0 + tx * 8 + j4;
      if (n < N) {  // N is a multiple of 8, microtile cols aligned to 8
        float4 v = make_float4(acc[i][j4], acc[i][j4 + 1], acc[i][j4 + 2], acc[i][j4 + 3]);
        *reinterpret_cast<float4*>(crow + n) = v;
      }
    }
  }
}

// ---------------- depthwise causal conv(4) + bias + silu ---------------------
// grid (8 ltiles, 5 ctiles, 8 batch), 128 threads (one channel each).
__global__ __launch_bounds__(128) void conv_silu_kernel(
    const float* __restrict__ zx, const float* __restrict__ cw,
    const float* __restrict__ cb, float* __restrict__ out) {
  const int c  = blockIdx.y * 128 + threadIdx.x;   // 0..639
  const int b  = blockIdx.z;
  const int l0 = blockIdx.x * 128;
  const float w0 = cw[c * 4 + 0], w1 = cw[c * 4 + 1];
  const float w2 = cw[c * 4 + 2], w3 = cw[c * 4 + 3];
  const float bias = cb[c];
  const float* src = zx + (size_t)b * LSEQ * DPROJ + DIN + c;
  float* dst = out + (size_t)b * LSEQ * CONVD + c;
  float x0 = 0.f, x1 = 0.f, x2 = 0.f;
  if (l0 > 0) {
    x0 = src[(size_t)(l0 - 3) * DPROJ];
    x1 = src[(size_t)(l0 - 2) * DPROJ];
    x2 = src[(size_t)(l0 - 1) * DPROJ];
  }
  for (int l = l0; l < l0 + 128; l++) {
    float xc = src[(size_t)l * DPROJ];
    float v = fmaf(w0, x0, fmaf(w1, x1, fmaf(w2, x2, fmaf(w3, xc, bias))));
    v = v / (1.f + expf(-v));       // silu
    dst[(size_t)l * CONVD] = v;
    x0 = x1; x1 = x2; x2 = xc;
  }
}

// ---------------- dt = softplus(raw + bias);  dA = exp(dt * A) ---------------
__global__ __launch_bounds__(256) void dt_dA_kernel(
    const float* __restrict__ zx, const float* __restrict__ dtb,
    const float* __restrict__ alog, float* __restrict__ dt_out,
    float* __restrict__ dA_out) {
  int idx = blockIdx.x * 256 + threadIdx.x;   // < BL*NH
  if (idx >= BL * NH) return;
  int hh = idx & 7;
  int row = idx >> 3;
  float raw = zx[(size_t)row * DPROJ + (DPROJ - NH) + hh] + dtb[hh];
  float dtv = raw > 20.f ? raw : log1pf(expf(raw));
  float A = -expf(alog[hh]);
  dt_out[idx] = dtv;
  dA_out[idx] = expf(dtv * A);
}

// ---------------- SSM scan -------------------------------------------------
// grid (64 = b*h, 2 = p-half), 256 threads.
// thread t: pl = t>>3 (32 p rows), n-range n0=(t&7)*8 .. +8, 8 state regs.
__global__ __launch_bounds__(256) void scan_kernel(
    const float* __restrict__ xbc, const float* __restrict__ dt,
    const float* __restrict__ dA, const float* __restrict__ Dp,
    float* __restrict__ ypre) {
  const int bh = blockIdx.x;
  const int b = bh >> 3, h = bh & 7;
  const int p0 = blockIdx.y * 32;
  const int t = threadIdx.x;
  const int pl = t >> 3;
  const int n0 = (t & 7) * 8;
  const float Dh = Dp[h];

  __shared__ float sx[64][32];   // also reused as the y chunk buffer
  __shared__ float sB[64][64];
  __shared__ float sC[64][64];
  __shared__ float sdt[64];
  __shared__ float sda[64];

  float s[8];
#pragma unroll
  for (int k = 0; k < 8; k++) s[k] = 0.f;

  const size_t row0 = (size_t)b * LSEQ;
  for (int l0 = 0; l0 < LSEQ; l0 += 64) {
    for (int i = t; i < 64 * 32; i += 256) {
      int r = i >> 5, cc = i & 31;
      sx[r][cc] = xbc[(row0 + l0 + r) * CONVD + h * HD + p0 + cc];
    }
    for (int i = t; i < 64 * 64; i += 256) {
      int r = i >> 6, cc = i & 63;
      sB[r][cc] = xbc[(row0 + l0 + r) * CONVD + DIN + cc];
      sC[r][cc] = xbc[(row0 + l0 + r) * CONVD + DIN + DS + cc];
    }
    if (t < 64) {
      sdt[t] = dt[(row0 + l0 + t) * NH + h];
      sda[t] = dA[(row0 + l0 + t) * NH + h];
    }
    __syncthreads();

    for (int l = 0; l < 64; l++) {
      float a = sda[l];
      float xv = sx[l][pl];
      float coef = sdt[l] * xv;
      float yp = 0.f;
#pragma unroll
      for (int k = 0; k < 8; k++) {
        s[k] = fmaf(s[k], a, coef * sB[l][n0 + k]);
        yp = fmaf(s[k], sC[l][n0 + k], yp);
      }
      yp += __shfl_down_sync(0xffffffffu, yp, 4, 8);
      yp += __shfl_down_sync(0xffffffffu, yp, 2, 8);
      yp += __shfl_down_sync(0xffffffffu, yp, 1, 8);
      // all 8 lanes of the group already read sx[l][pl]; shuffles synced them.
      if ((t & 7) == 0) sx[l][pl] = yp + Dh * xv;   // reuse sx for y output
    }
    __syncthreads();

    for (int i = t; i < 64 * 32; i += 256) {
      int r = i >> 5, cc = i & 31;
      ypre[(row0 + l0 + r) * DIN + h * HD + p0 + cc] = sx[r][cc];
    }
    __syncthreads();
  }
}

// ---------------- y = (ypre * silu(z)), RMSnorm over 512, * norm_w -----------
__global__ __launch_bounds__(128) void gate_norm_kernel(
    const float* __restrict__ ypre, const float* __restrict__ zx,
    const float* __restrict__ nw, float* __restrict__ out) {
  const int row = blockIdx.x;     // 8192
  const int t = threadIdx.x;      // 128
  float v[4];
  float ss = 0.f;
#pragma unroll
  for (int i = 0; i < 4; i++) {
    int c = t + i * 128;
    float y = ypre[(size_t)row * DIN + c];
    float z = zx[(size_t)row * DPROJ + c];
    float g = z / (1.f + expf(-z));
    float val = y * g;
    v[i] = val;
    ss += val * val;
  }
#pragma unroll
  for (int o = 16; o > 0; o >>= 1) ss += __shfl_down_sync(0xffffffffu, ss, o);
  __shared__ float ws[4];
  if ((t & 31) == 0) ws[t >> 5] = ss;
  __syncthreads();
  float tot = ws[0] + ws[1] + ws[2] + ws[3];
  float scale = rsqrtf(tot * (1.f / 512.f) + 1e-5f);
#pragma unroll
  for (int i = 0; i < 4; i++) {
    int c = t + i * 128;
    out[(size_t)row * DIN + c] = v[i] * scale * nw[c];
  }
}

// ---------------- launch ----------------------------------------------------
extern "C" void kernel_launch(void* const* d_in, const int* in_sizes, int n_in,
                              void* d_out, int out_size) {
  const float* x    = (const float*)d_in[0];  // (8,32,32,256) == (8192,256)
  const float* wi   = (const float*)d_in[1];  // (2,1160,256)
  const float* cw   = (const float*)d_in[2];  // (2,640,1,4)
  const float* cb   = (const float*)d_in[3];  // (2,640)
  const float* dtb  = (const float*)d_in[4];  // (2,8)
  const float* alog = (const float*)d_in[5];  // (2,8)
  const float* Dp   = (const float*)d_in[6];  // (2,8)
  const float* nw   = (const float*)d_in[7];  // (2,512)
  const float* wo   = (const float*)d_in[8];  // (2,256,512)
  float* out = (float*)d_out;

  float *p_zx, *p_xbc, *p_dt, *p_dA, *p_ypre, *p_ynorm, *p_h;
  cudaGetSymbolAddress((void**)&p_zx, g_zx);
  cudaGetSymbolAddress((void**)&p_xbc, g_xbc);
  cudaGetSymbolAddress((void**)&p_dt, g_dt);
  cudaGetSymbolAddress((void**)&p_dA, g_dA);
  cudaGetSymbolAddress((void**)&p_ypre, g_ypre);
  cudaGetSymbolAddress((void**)&p_ynorm, g_ynorm);
  cudaGetSymbolAddress((void**)&p_h, g_h);

  for (int i = 0; i < 2; i++) {
    const float* hin = (i == 0) ? x : p_h;
    float* hout = (i == 1) ? out : p_h;

    // in_proj: (8192,1160) = h (8192,256) @ wi^T
    sgemm_nt<<<dim3((DPROJ + 127) / 128, BL / 128), 256>>>(
        hin, wi + (size_t)i * DPROJ * DM, p_zx, BL, DPROJ, DM);

    // conv + silu on xBC channels
    conv_silu_kernel<<<dim3(LSEQ / 128, CONVD / 128, BATCH), 128>>>(
        p_zx, cw + (size_t)i * CONVD * 4, cb + (size_t)i * CONVD, p_xbc);

    // dt / dA
    dt_dA_kernel<<<(BL * NH + 255) / 256, 256>>>(
        p_zx, dtb + i * NH, alog + i * NH, p_dt, p_dA);

    // SSM scan (+ D*x skip)
    scan_kernel<<<dim3(BATCH * NH, 2), 256>>>(
        p_xbc, p_dt, p_dA, Dp + i * NH, p_ypre);

    // gate by silu(z), RMSnorm, * norm_w
    gate_norm_kernel<<<BL, 128>>>(p_ypre, p_zx, nw + (size_t)i * DIN, p_ynorm);

    // out_proj: (8192,256) = ynorm (8192,512) @ wo^T
    sgemm_nt<<<dim3(DM / 128, BL / 128), 256>>>(
        p_ynorm, wo + (size_t)i * DM * DIN, hout, BL, DM, DIN);
  }
}

// round 9
// speedup vs baseline: 1.1314x; 1.1314x over previous
#include <cuda_runtime.h>
#include <math.h>

#define BATCH 8
#define LSEQ  1024
#define BL    8192
#define DM    256
#define DIN   512
#define DPROJ 1160
#define CONVD 640
#define NH    8
#define HD    64
#define DS    64

// ---------------- scratch (device globals; no runtime allocation) ------------
__device__ float g_zx[BL * DPROJ];    // in_proj output (zxbcdt)     ~38 MB
__device__ float g_xbc[BL * CONVD];   // conv+silu output            ~21 MB
__device__ float g_dt[BL * NH];
__device__ float g_dA[BL * NH];
__device__ float g_ypre[BL * DIN];    // scan output incl. D*x       ~17 MB
__device__ float g_ynorm[BL * DIN];   // gated + rmsnormed
__device__ float g_h[BL * DM];        // hidden between the 2 blocks

// ---------------- SGEMM: C[M,N] = A[M,K] * W[N,K]^T  (both K-contiguous) -----
__global__ __launch_bounds__(256) void sgemm_nt(
    const float* __restrict__ A, const float* __restrict__ W,
    float* __restrict__ C, int M, int N, int K) {
  __shared__ float As[16][128];
  __shared__ float Ws[16][128];
  const int tid = threadIdx.x;
  const int tx = tid & 15;        // n-dir
  const int ty = tid >> 4;        // m-dir
  const int m0 = blockIdx.y * 128;
  const int n0 = blockIdx.x * 128;
  const int lr = tid >> 2;        // 0..63 row for loads
  const int lc = (tid & 3) * 4;   // 0,4,8,12 col for loads

  float acc[8][8];
#pragma unroll
  for (int i = 0; i < 8; i++)
#pragma unroll
    for (int j = 0; j < 8; j++) acc[i][j] = 0.f;

  for (int k0 = 0; k0 < K; k0 += 16) {
#pragma unroll
    for (int rr = 0; rr < 2; rr++) {
      int m = m0 + lr + rr * 64;
      float4 v = *reinterpret_cast<const float4*>(A + (size_t)m * K + k0 + lc);
      As[lc + 0][lr + rr * 64] = v.x;
      As[lc + 1][lr + rr * 64] = v.y;
      As[lc + 2][lr + rr * 64] = v.z;
      As[lc + 3][lr + rr * 64] = v.w;
    }
#pragma unroll
    for (int rr = 0; rr < 2; rr++) {
      int n = n0 + lr + rr * 64;
      float4 v = make_float4(0.f, 0.f, 0.f, 0.f);
      if (n < N)
        v = *reinterpret_cast<const float4*>(W + (size_t)n * K + k0 + lc);
      Ws[lc + 0][lr + rr * 64] = v.x;
      Ws[lc + 1][lr + rr * 64] = v.y;
      Ws[lc + 2][lr + rr * 64] = v.z;
      Ws[lc + 3][lr + rr * 64] = v.w;
    }
    __syncthreads();
#pragma unroll
    for (int kk = 0; kk < 16; kk++) {
      float a[8], b[8];
      *reinterpret_cast<float4*>(&a[0]) = *reinterpret_cast<const float4*>(&As[kk][ty * 8]);
      *reinterpret_cast<float4*>(&a[4]) = *reinterpret_cast<const float4*>(&As[kk][ty * 8 + 4]);
      *reinterpret_cast<float4*>(&b[0]) = *reinterpret_cast<const float4*>(&Ws[kk][tx * 8]);
      *reinterpret_cast<float4*>(&b[4]) = *reinterpret_cast<const float4*>(&Ws[kk][tx * 8 + 4]);
#pragma unroll
      for (int i = 0; i < 8; i++)
#pragma unroll
        for (int j = 0; j < 8; j++)
          acc[i][j] = fmaf(a[i], b[j], acc[i][j]);
    }
    __syncthreads();
  }

#pragma unroll
  for (int i = 0; i < 8; i++) {
    int m = m0 + ty * 8 + i;
    float* crow = C + (size_t)m * N;
#pragma unroll
    for (int j4 = 0; j4 < 8; j4 += 4) {
      int n = n0 + tx * 8 + j4;
      if (n < N) {
        float4 v = make_float4(acc[i][j4], acc[i][j4 + 1], acc[i][j4 + 2], acc[i][j4 + 3]);
        *reinterpret_cast<float4*>(crow + n) = v;
      }
    }
  }
}

// ---------------- depthwise causal conv(4) + bias + silu ---------------------
__global__ __launch_bounds__(128) void conv_silu_kernel(
    const float* __restrict__ zx, const float* __restrict__ cw,
    const float* __restrict__ cb, float* __restrict__ out) {
  const int c  = blockIdx.y * 128 + threadIdx.x;   // 0..639
  const int b  = blockIdx.z;
  const int l0 = blockIdx.x * 128;
  const float w0 = cw[c * 4 + 0], w1 = cw[c * 4 + 1];
  const float w2 = cw[c * 4 + 2], w3 = cw[c * 4 + 3];
  const float bias = cb[c];
  const float* src = zx + (size_t)b * LSEQ * DPROJ + DIN + c;
  float* dst = out + (size_t)b * LSEQ * CONVD + c;
  float x0 = 0.f, x1 = 0.f, x2 = 0.f;
  if (l0 > 0) {
    x0 = src[(size_t)(l0 - 3) * DPROJ];
    x1 = src[(size_t)(l0 - 2) * DPROJ];
    x2 = src[(size_t)(l0 - 1) * DPROJ];
  }
  for (int l = l0; l < l0 + 128; l++) {
    float xc = src[(size_t)l * DPROJ];
    float v = fmaf(w0, x0, fmaf(w1, x1, fmaf(w2, x2, fmaf(w3, xc, bias))));
    v = __fdividef(v, 1.f + __expf(-v));       // silu (fast path)
    dst[(size_t)l * CONVD] = v;
    x0 = x1; x1 = x2; x2 = xc;
  }
}

// ---------------- dt = softplus(raw + bias);  dA = exp(dt * A) ---------------
__global__ __launch_bounds__(256) void dt_dA_kernel(
    const float* __restrict__ zx, const float* __restrict__ dtb,
    const float* __restrict__ alog, float* __restrict__ dt_out,
    float* __restrict__ dA_out) {
  int idx = blockIdx.x * 256 + threadIdx.x;   // < BL*NH
  if (idx >= BL * NH) return;
  int hh = idx & 7;
  int row = idx >> 3;
  float raw = zx[(size_t)row * DPROJ + (DPROJ - NH) + hh] + dtb[hh];
  float dtv = raw > 20.f ? raw : log1pf(__expf(raw));
  float A = -__expf(alog[hh]);
  dt_out[idx] = dtv;
  dA_out[idx] = __expf(dtv * A);
}

// ---------------- SSM scan -------------------------------------------------
// grid (64 = b*h, 4 = p-quarter), 256 threads.
// thread t: pl = t>>4 (16 p rows), n-range n0=(t&15)*4 .. +4, 4 state regs.
// 2 CTAs/SM resident (smem ~37KB, regs low) -> 16 warps for latency hiding.
__global__ __launch_bounds__(256) void scan_kernel(
    const float* __restrict__ xbc, const float* __restrict__ dt,
    const float* __restrict__ dA, const float* __restrict__ Dp,
    float* __restrict__ ypre) {
  const int bh = blockIdx.x;
  const int b = bh >> 3, h = bh & 7;
  const int p0 = blockIdx.y * 16;
  const int t = threadIdx.x;
  const int pl = t >> 4;          // 0..15 : p row within block
  const int nl = t & 15;          // 0..15 : n lane group
  const int n0 = nl * 4;
  const float Dh = Dp[h];

  __shared__ float sx[64][16];   // also reused as the y chunk buffer
  __shared__ float sB[64][64];
  __shared__ float sC[64][64];
  __shared__ float sdt[64];
  __shared__ float sda[64];

  float s[4];
#pragma unroll
  for (int k = 0; k < 4; k++) s[k] = 0.f;

  const size_t row0 = (size_t)b * LSEQ;
  for (int l0 = 0; l0 < LSEQ; l0 += 64) {
    for (int i = t; i < 64 * 16; i += 256) {
      int r = i >> 4, cc = i & 15;
      sx[r][cc] = xbc[(row0 + l0 + r) * CONVD + h * HD + p0 + cc];
    }
    for (int i = t; i < 64 * 64; i += 256) {
      int r = i >> 6, cc = i & 63;
      sB[r][cc] = xbc[(row0 + l0 + r) * CONVD + DIN + cc];
      sC[r][cc] = xbc[(row0 + l0 + r) * CONVD + DIN + DS + cc];
    }
    if (t < 64) {
      sdt[t] = dt[(row0 + l0 + t) * NH + h];
      sda[t] = dA[(row0 + l0 + t) * NH + h];
    }
    __syncthreads();

    for (int l = 0; l < 64; l++) {
      float a = sda[l];
      float xv = sx[l][pl];
      float coef = sdt[l] * xv;
      float yp = 0.f;
#pragma unroll
      for (int k = 0; k < 4; k++) {
        s[k] = fmaf(s[k], a, coef * sB[l][n0 + k]);
        yp = fmaf(s[k], sC[l][n0 + k], yp);
      }
      yp += __shfl_down_sync(0xffffffffu, yp, 8, 16);
      yp += __shfl_down_sync(0xffffffffu, yp, 4, 16);
      yp += __shfl_down_sync(0xffffffffu, yp, 2, 16);
      yp += __shfl_down_sync(0xffffffffu, yp, 1, 16);
      // each pl column is owned by exactly one warp (16 lanes); safe to
      // overwrite sx[l][pl] once all its lanes have consumed xv this step.
      if (nl == 0) sx[l][pl] = yp + Dh * xv;   // reuse sx for y output
    }
    __syncthreads();

    for (int i = t; i < 64 * 16; i += 256) {
      int r = i >> 4, cc = i & 15;
      ypre[(row0 + l0 + r) * DIN + h * HD + p0 + cc] = sx[r][cc];
    }
    __syncthreads();
  }
}

// ---------------- y = (ypre * silu(z)), RMSnorm over 512, * norm_w -----------
__global__ __launch_bounds__(128) void gate_norm_kernel(
    const float* __restrict__ ypre, const float* __restrict__ zx,
    const float* __restrict__ nw, float* __restrict__ out) {
  const int row = blockIdx.x;     // 8192
  const int t = threadIdx.x;      // 128
  float v[4];
  float ss = 0.f;
#pragma unroll
  for (int i = 0; i < 4; i++) {
    int c = t + i * 128;
    float y = ypre[(size_t)row * DIN + c];
    float z = zx[(size_t)row * DPROJ + c];
    float g = __fdividef(z, 1.f + __expf(-z));
    float val = y * g;
    v[i] = val;
    ss += val * val;
  }
#pragma unroll
  for (int o = 16; o > 0; o >>= 1) ss += __shfl_down_sync(0xffffffffu, ss, o);
  __shared__ float ws[4];
  if ((t & 31) == 0) ws[t >> 5] = ss;
  __syncthreads();
  float tot = ws[0] + ws[1] + ws[2] + ws[3];
  float scale = rsqrtf(tot * (1.f / 512.f) + 1e-5f);
#pragma unroll
  for (int i = 0; i < 4; i++) {
    int c = t + i * 128;
    out[(size_t)row * DIN + c] = v[i] * scale * nw[c];
  }
}

// ---------------- launch ----------------------------------------------------
extern "C" void kernel_launch(void* const* d_in, const int* in_sizes, int n_in,
                              void* d_out, int out_size) {
  const float* x    = (const float*)d_in[0];  // (8,32,32,256) == (8192,256)
  const float* wi   = (const float*)d_in[1];  // (2,1160,256)
  const float* cw   = (const float*)d_in[2];  // (2,640,1,4)
  const float* cb   = (const float*)d_in[3];  // (2,640)
  const float* dtb  = (const float*)d_in[4];  // (2,8)
  const float* alog = (const float*)d_in[5];  // (2,8)
  const float* Dp   = (const float*)d_in[6];  // (2,8)
  const float* nw   = (const float*)d_in[7];  // (2,512)
  const float* wo   = (const float*)d_in[8];  // (2,256,512)
  float* out = (float*)d_out;

  float *p_zx, *p_xbc, *p_dt, *p_dA, *p_ypre, *p_ynorm, *p_h;
  cudaGetSymbolAddress((void**)&p_zx, g_zx);
  cudaGetSymbolAddress((void**)&p_xbc, g_xbc);
  cudaGetSymbolAddress((void**)&p_dt, g_dt);
  cudaGetSymbolAddress((void**)&p_dA, g_dA);
  cudaGetSymbolAddress((void**)&p_ypre, g_ypre);
  cudaGetSymbolAddress((void**)&p_ynorm, g_ynorm);
  cudaGetSymbolAddress((void**)&p_h, g_h);

  for (int i = 0; i < 2; i++) {
    const float* hin = (i == 0) ? x : p_h;
    float* hout = (i == 1) ? out : p_h;

    // in_proj: (8192,1160) = h (8192,256) @ wi^T
    sgemm_nt<<<dim3((DPROJ + 127) / 128, BL / 128), 256>>>(
        hin, wi + (size_t)i * DPROJ * DM, p_zx, BL, DPROJ, DM);

    // conv + silu on xBC channels
    conv_silu_kernel<<<dim3(LSEQ / 128, CONVD / 128, BATCH), 128>>>(
        p_zx, cw + (size_t)i * CONVD * 4, cb + (size_t)i * CONVD, p_xbc);

    // dt / dA
    dt_dA_kernel<<<(BL * NH + 255) / 256, 256>>>(
        p_zx, dtb + i * NH, alog + i * NH, p_dt, p_dA);

    // SSM scan (+ D*x skip): 4-way p split for 2 CTAs/SM
    scan_kernel<<<dim3(BATCH * NH, 4), 256>>>(
        p_xbc, p_dt, p_dA, Dp + i * NH, p_ypre);

    // gate by silu(z), RMSnorm, * norm_w
    gate_norm_kernel<<<BL, 128>>>(p_ypre, p_zx, nw + (size_t)i * DIN, p_ynorm);

    // out_proj: (8192,256) = ynorm (8192,512) @ wo^T
    sgemm_nt<<<dim3(DM / 128, BL / 128), 256>>>(
        p_ynorm, wo + (size_t)i * DM * DIN, hout, BL, DM, DIN);
  }
}